// round 1
// baseline (speedup 1.0000x reference)
#include <cuda_runtime.h>
#include <cstdint>

#define NB 32
#define H1 224
#define W1 224
#define P1 (H1*W1)      // 50176
#define H2 112
#define P2 (H2*H2)      // 12544
#define H3 56
#define P3 (H3*H3)      // 3136

// ---------------- scratch (static __device__, allocation-free) ----------------
__device__ uint32_t            g_binx[NB*P1];   // 3 bits/pixel (input signs)
__device__ uint32_t            g_h1[NB*P1];     // 32 ch packed
__device__ unsigned long long  g_h2[NB*P2];     // 64 ch packed
__device__ int                 g_cnt[NB*128];   // count of -1 per (b, oc) in layer3
__device__ uint32_t            g_w1[32];        // 27-bit packed weights
__device__ uint32_t            g_w2[64*9];      // per-tap 32-bit packed
__device__ unsigned long long  g_w3[128*9];     // per-tap 64-bit packed
__device__ int g_T1[32];  __device__ int g_F1[32];
__device__ int g_T2[64];  __device__ int g_F2[64];
__device__ int g_T3[128]; __device__ int g_F3[128];

// -------- integer threshold for sign(BN(a)) with exact fp32 semantics --------
// bit(=1 means -1) = ( __fadd_rn(__fmul_rn(a,inv), c0) < 0 )
// monotone in a -> representable as (a < T) ^ F
__device__ __forceinline__ void calc_thresh(float g, float bb, float m, float v,
                                            int K, int* T, int* F)
{
    float inv = __fdiv_rn(g, sqrtf(__fadd_rn(v, 1e-5f)));
    float c0  = __fsub_rn(bb, __fmul_rn(m, inv));
    if (inv > 0.f) {
        int A0 = K + 1;                      // smallest a with f >= 0
        for (int a = -K; a <= K; a++) {
            float f = __fadd_rn(__fmul_rn((float)a, inv), c0);
            if (f >= 0.f) { A0 = a; break; }
        }
        *T = A0; *F = 0;                     // bit = (a < A0)
    } else if (inv < 0.f) {
        int A1 = -K - 1;                     // largest a with f >= 0
        for (int a = K; a >= -K; a--) {
            float f = __fadd_rn(__fmul_rn((float)a, inv), c0);
            if (f >= 0.f) { A1 = a; break; }
        }
        *T = A1 + 1; *F = 1;                 // bit = !(a < A1+1)
    } else {
        // f == c0 (with signed-zero care matching IEEE add)
        if (c0 < 0.f) { *T =  K + 1;  *F = 0; }   // always -1
        else          { *T = -(K+1);  *F = 0; }   // always +1
    }
}

// ---------------- precompute: pack weights + thresholds ----------------
__global__ void precompute_kernel(
    const float* w1, const float* w2, const float* w3,
    const float* g1, const float* b1, const float* m1, const float* v1,
    const float* g2, const float* b2, const float* m2, const float* v2,
    const float* g3, const float* b3, const float* m3, const float* v3)
{
    int t = threadIdx.x;
    if (t < 32) {
        uint32_t bits = 0;
        for (int ic = 0; ic < 3; ic++)
            for (int kh = 0; kh < 3; kh++)
                for (int kw = 0; kw < 3; kw++)
                    if (w1[((t*3 + ic)*3 + kh)*3 + kw] < 0.f)
                        bits |= 1u << ((kh*3 + kw)*3 + ic);
        g_w1[t] = bits;
        calc_thresh(g1[t], b1[t], m1[t], v1[t], 27, &g_T1[t], &g_F1[t]);
    }
    if (t < 64) {
        for (int tap = 0; tap < 9; tap++) {
            int kh = tap / 3, kw = tap % 3;
            uint32_t bits = 0;
            for (int ic = 0; ic < 32; ic++)
                if (w2[((t*32 + ic)*3 + kh)*3 + kw] < 0.f) bits |= 1u << ic;
            g_w2[t*9 + tap] = bits;
        }
        calc_thresh(g2[t], b2[t], m2[t], v2[t], 288, &g_T2[t], &g_F2[t]);
    }
    if (t < 128) {
        for (int tap = 0; tap < 9; tap++) {
            int kh = tap / 3, kw = tap % 3;
            unsigned long long bits = 0;
            for (int ic = 0; ic < 64; ic++)
                if (w3[((t*64 + ic)*3 + kh)*3 + kw] < 0.f) bits |= 1ull << ic;
            g_w3[t*9 + tap] = bits;
        }
        calc_thresh(g3[t], b3[t], m3[t], v3[t], 576, &g_T3[t], &g_F3[t]);
    }
}

// ---------------- binarize input: [B,3,224,224] -> 3 bits/pixel ----------------
__global__ void binx_kernel(const float* __restrict__ x)
{
    int i = blockIdx.x * blockDim.x + threadIdx.x;
    if (i >= NB*P1) return;
    int b = i / P1, p = i % P1;
    const float* xb = x + (size_t)b * 3 * P1 + p;
    uint32_t bits = (xb[0]      < 0.f ? 1u : 0u)
                  | (xb[P1]     < 0.f ? 2u : 0u)
                  | (xb[2*P1]   < 0.f ? 4u : 0u);
    g_binx[i] = bits;
}

// ---------------- layer 1: 3ch -> 32ch, stride 1, pad 1 ----------------
__global__ void layer1_kernel()
{
    __shared__ uint32_t sw[32];
    __shared__ int sT[32], sF[32];
    if (threadIdx.x < 32) {
        sw[threadIdx.x] = g_w1[threadIdx.x];
        sT[threadIdx.x] = g_T1[threadIdx.x];
        sF[threadIdx.x] = g_F1[threadIdx.x];
    }
    __syncthreads();

    int i = blockIdx.x * blockDim.x + threadIdx.x;
    if (i >= NB*P1) return;
    int b = i / P1, p = i % P1;
    int oh = p / W1, ow = p % W1;

    const uint32_t* bx = &g_binx[b * P1];
    uint32_t xv = 0, mask = 0;
    #pragma unroll
    for (int kh = 0; kh < 3; kh++) {
        int ih = oh + kh - 1;
        #pragma unroll
        for (int kw = 0; kw < 3; kw++) {
            int iw = ow + kw - 1;
            if ((unsigned)ih < (unsigned)H1 && (unsigned)iw < (unsigned)W1) {
                int tap = kh*3 + kw;
                xv   |= bx[ih*W1 + iw] << (tap*3);
                mask |= 7u << (tap*3);
            }
        }
    }
    int base = __popc(mask);          // number of valid ±1 products
    uint32_t out = 0;
    #pragma unroll
    for (int oc = 0; oc < 32; oc++) {
        int s = __popc((xv ^ sw[oc]) & mask);
        int a = base - 2*s;
        uint32_t bit = (uint32_t)(((a < sT[oc]) ? 1 : 0) ^ sF[oc]) & 1u;
        out |= bit << oc;
    }
    g_h1[i] = out;
}

// ---------------- layer 2: 32ch -> 64ch, stride 2, pad 1 ----------------
__global__ void layer2_kernel()
{
    __shared__ uint32_t sw[64*9];
    __shared__ int sT[64], sF[64];
    for (int j = threadIdx.x; j < 64*9; j += blockDim.x) sw[j] = g_w2[j];
    if (threadIdx.x < 64) {
        sT[threadIdx.x] = g_T2[threadIdx.x];
        sF[threadIdx.x] = g_F2[threadIdx.x];
    }
    __syncthreads();

    int i = blockIdx.x * blockDim.x + threadIdx.x;
    if (i >= NB*P2) return;
    int b = i / P2, p = i % P2;
    int oh = p / H2, ow = p % H2;

    const uint32_t* h1b = &g_h1[b * P1];
    uint32_t xw[9], mk[9];
    int V = 0;
    #pragma unroll
    for (int kh = 0; kh < 3; kh++) {
        int ih = 2*oh + kh - 1;
        #pragma unroll
        for (int kw = 0; kw < 3; kw++) {
            int iw = 2*ow + kw - 1;
            int t = kh*3 + kw;
            bool ok = ((unsigned)ih < 224u) && ((unsigned)iw < 224u);
            xw[t] = ok ? h1b[ih*224 + iw] : 0u;
            mk[t] = ok ? 0xFFFFFFFFu : 0u;
            V += ok ? 1 : 0;
        }
    }
    int base = 32 * V;
    unsigned long long out = 0;
    for (int oc = 0; oc < 64; oc++) {
        int s = 0;
        #pragma unroll
        for (int t = 0; t < 9; t++)
            s += __popc((xw[t] ^ sw[oc*9 + t]) & mk[t]);
        int a = base - 2*s;
        unsigned long long bit =
            (unsigned long long)((((a < sT[oc]) ? 1 : 0) ^ sF[oc]) & 1);
        out |= bit << oc;
    }
    g_h2[i] = out;
}

// ---------------- layer 3: 64ch -> 128ch, stride 2, pad 1, + count for avgpool ----
__global__ void layer3_kernel()
{
    __shared__ unsigned long long sw[128*9];
    __shared__ int sT[128], sF[128], scnt[128];
    for (int j = threadIdx.x; j < 128*9; j += blockDim.x) sw[j] = g_w3[j];
    if (threadIdx.x < 128) {
        sT[threadIdx.x]   = g_T3[threadIdx.x];
        sF[threadIdx.x]   = g_F3[threadIdx.x];
        scnt[threadIdx.x] = 0;
    }
    __syncthreads();

    int b = blockIdx.x;
    int p = blockIdx.y * blockDim.x + threadIdx.x;
    int valid = (p < P3) ? 1 : 0;
    int pp = valid ? p : 0;
    int oh = pp / H3, ow = pp % H3;

    const unsigned long long* h2b = &g_h2[b * P2];
    unsigned long long xw[9], mk[9];
    int V = 0;
    #pragma unroll
    for (int kh = 0; kh < 3; kh++) {
        int ih = 2*oh + kh - 1;
        #pragma unroll
        for (int kw = 0; kw < 3; kw++) {
            int iw = 2*ow + kw - 1;
            int t = kh*3 + kw;
            bool ok = valid && ((unsigned)ih < 112u) && ((unsigned)iw < 112u);
            xw[t] = ok ? h2b[ih*112 + iw] : 0ull;
            mk[t] = ok ? ~0ull : 0ull;
            V += ok ? 1 : 0;
        }
    }
    int base = 64 * V;
    int lane = threadIdx.x & 31;
    for (int oc = 0; oc < 128; oc++) {
        int s = 0;
        #pragma unroll
        for (int t = 0; t < 9; t++)
            s += __popcll((xw[t] ^ sw[oc*9 + t]) & mk[t]);
        int a = base - 2*s;
        unsigned bit = (unsigned)(((((a < sT[oc]) ? 1 : 0) ^ sF[oc]) & 1) & valid);
        unsigned bal = __ballot_sync(0xFFFFFFFFu, bit);
        if (lane == 0) atomicAdd(&scnt[oc], __popc(bal));
    }
    __syncthreads();
    if (threadIdx.x < 128)
        atomicAdd(&g_cnt[b*128 + threadIdx.x], scnt[threadIdx.x]);
}

// ---------------- helpers ----------------
__global__ void zero_cnt_kernel()
{
    int i = blockIdx.x * blockDim.x + threadIdx.x;
    if (i < NB*128) g_cnt[i] = 0;
}

__global__ void fc_kernel(const float* __restrict__ fcw,
                          const float* __restrict__ fcb,
                          float* __restrict__ out)
{
    int t = threadIdx.x;
    if (t >= NB*2) return;
    int b = t >> 1, k = t & 1;
    float s = fcb[k];
    const float* wr = fcw + k*128;
    for (int c = 0; c < 128; c++) {
        // mean over 3136 of ±1 = (pos - neg)/3136 = (3136 - 2*cnt_neg)/3136
        float mean = (float)(P3 - 2*g_cnt[b*128 + c]) / (float)P3;
        s += mean * wr[c];
    }
    out[b*2 + k] = s;
}

// ---------------- launch ----------------
extern "C" void kernel_launch(void* const* d_in, const int* in_sizes, int n_in,
                              void* d_out, int out_size)
{
    const float* x   = (const float*)d_in[0];
    const float* w1  = (const float*)d_in[1];
    const float* w2  = (const float*)d_in[2];
    const float* w3  = (const float*)d_in[3];
    const float* g1  = (const float*)d_in[4];
    const float* b1  = (const float*)d_in[5];
    const float* m1  = (const float*)d_in[6];
    const float* v1  = (const float*)d_in[7];
    const float* g2  = (const float*)d_in[8];
    const float* b2  = (const float*)d_in[9];
    const float* m2  = (const float*)d_in[10];
    const float* v2  = (const float*)d_in[11];
    const float* g3  = (const float*)d_in[12];
    const float* b3  = (const float*)d_in[13];
    const float* m3  = (const float*)d_in[14];
    const float* v3  = (const float*)d_in[15];
    const float* fcw = (const float*)d_in[16];
    const float* fcb = (const float*)d_in[17];
    float* out = (float*)d_out;

    precompute_kernel<<<1, 256>>>(w1, w2, w3,
                                  g1, b1, m1, v1,
                                  g2, b2, m2, v2,
                                  g3, b3, m3, v3);

    int n1 = NB * P1;                       // 1,605,632
    binx_kernel<<<(n1 + 255)/256, 256>>>(x);
    layer1_kernel<<<(n1 + 255)/256, 256>>>();

    int n2 = NB * P2;                       // 401,408
    layer2_kernel<<<(n2 + 255)/256, 256>>>();

    zero_cnt_kernel<<<16, 256>>>();
    dim3 grid3(NB, (P3 + 255)/256);         // 32 x 13
    layer3_kernel<<<grid3, 256>>>();

    fc_kernel<<<1, 64>>>(fcw, fcb, out);
}